// round 12
// baseline (speedup 1.0000x reference)
#include <cuda_runtime.h>
#include <cstdint>
#include <math.h>

// y_true [B,1024] fp32, target [B,1024] fp32 -> scalar fp32 loss.
#define NCOLS   1024
#define NBLK    592            // 148 SMs * 4 resident blocks (smem-capped)
#define NWARPS  (NBLK * 8)

__device__ double g_pt[NBLK];
__device__ double g_ce[NBLK];
__device__ unsigned int g_count = 0;   // last-block-done counter

__device__ __forceinline__ float wval(int x) {
    const int pc = __popc(x);
    float w = ((pc & 1) ? 6.0f       : 1.0f)
            * ((pc & 2) ? 36.0f      : 1.0f)
            * ((pc & 4) ? 1296.0f    : 1.0f)
            * ((pc & 8) ? 1679616.0f : 1.0f);
    return (x == 0) ? 0.0f : w;   // 6^popc(x), zeroed at x==0; exact in fp32
}

__device__ __forceinline__ void cp16(unsigned int saddr, const void* gaddr) {
    asm volatile("cp.async.cg.shared.global [%0], [%1], 16;" :: "r"(saddr), "l"(gaddr));
}

// ---------------------------------------------------------------------------
// One-row software pipeline + cp.async target staging (zero register cost):
//   (1) cp.async target row b+1 -> smem slice     [no regs consumed]
//   (2) REDUX on carried (best,bidx) -> t for row b    [no wait]
//   (3) FMA carried yv (row b, loaded last iter)       [no wait]
//   (4) issue y LDG.128 for row b+1 -> yv
//   (5) wait cp.async; per-lane compare from smem -> carried (best,bidx)
// Only step (5) can wait, and its latency is covered by (2)-(4) plus 32
// warps/SM of oversubscription.
// ---------------------------------------------------------------------------
__global__ void __launch_bounds__(256, 4)
fused_kernel(const float* __restrict__ y, const float* __restrict__ target,
             float* __restrict__ out, int B) {
    // smem: [0,16K) W tables; [16K,48K) per-warp target slices (4KB each).
    // Finale partials alias into the W region after the post-loop barrier.
    __shared__ __align__(16) char smem_raw[49152];
    float (*W)[NCOLS] = reinterpret_cast<float (*)[NCOLS]>(smem_raw);
    char* tbuf = smem_raw + 16384;

    const int tid  = threadIdx.x;
    const int lane = tid & 31;
    const int wid  = tid >> 5;

    // W[p][i] = wval(i ^ p): weights of columns 4g..4g+3 for class t are the
    // aligned float4 at W[t&3][4*(g ^ (t>>2))].
    for (int i = tid; i < NCOLS; i += 256) {
        #pragma unroll
        for (int p = 0; p < 4; p++) W[p][i] = wval(i ^ p);
    }
    __syncthreads();

    char* tslice = tbuf + wid * 4096;
    const unsigned int ts = (unsigned int)__cvta_generic_to_shared(tslice);

    const int gwarp = blockIdx.x * 8 + wid;
    float pt32 = 0.0f;   // fp32 within-warp is exact enough (budget ~140 abs)
    float ce32 = 0.0f;

    int   b = gwarp;
    float best = -1.0f;
    int   bidx = 0;
    float4 yv[8];

    if (b < B) {
        // Prologue: stage row b's target via cp.async; load row b's y;
        // per-lane argmax of row b's target.
        {
            const char* tp = (const char*)(target + (size_t)b * NCOLS);
            #pragma unroll
            for (int i = 0; i < 8; i++) {
                const int off = (i * 32 + lane) * 16;
                cp16(ts + off, tp + off);
            }
            asm volatile("cp.async.commit_group;");
            const float4* yp = reinterpret_cast<const float4*>(y + (size_t)b * NCOLS);
            #pragma unroll
            for (int i = 0; i < 8; i++) yv[i] = __ldcs(&yp[i * 32 + lane]);
            asm volatile("cp.async.wait_group 0;");
            #pragma unroll
            for (int i = 0; i < 8; i++) {
                const int c4 = i * 32 + lane;
                const float4 v = *reinterpret_cast<const float4*>(tslice + c4 * 16);
                const int base = c4 * 4;
                if (v.x > best) { best = v.x; bidx = base;     }
                if (v.y > best) { best = v.y; bidx = base + 1; }
                if (v.z > best) { best = v.z; bidx = base + 2; }
                if (v.w > best) { best = v.w; bidx = base + 3; }
            }
        }

        // Steady-state pipeline.
        for (;;) {
            int bn = b + NWARPS;
            const bool last = (bn >= B);
            if (last) bn = b;   // clamped prefetch: staged but never accumulated

            // (1) cp.async next target row into this warp's slice.
            {
                const char* tpn = (const char*)(target + (size_t)bn * NCOLS);
                #pragma unroll
                for (int i = 0; i < 8; i++) {
                    const int off = (i * 32 + lane) * 16;
                    cp16(ts + off, tpn + off);
                }
                asm volatile("cp.async.commit_group;");
            }

            // (2) cross-lane argmax for row b from carried (best,bidx): no wait.
            const unsigned int mybits  = __float_as_uint(best);
            const unsigned int maxbits = __reduce_max_sync(0xffffffffu, mybits);
            const unsigned int cand    = (mybits == maxbits) ? (unsigned int)bidx
                                                             : 0xffffffffu;
            const int t  = (int)__reduce_min_sync(0xffffffffu, cand);
            const int tg = t >> 2;
            const float* Wt = W[t & 3];

            // (3) FMA carried yv (row b, loaded one iteration ago): no wait.
            float s0 = 0.f, s1 = 0.f, s2 = 0.f, s3 = 0.f;
            float yt = -1.0f;
            #pragma unroll
            for (int i = 0; i < 8; i++) {
                const int c4 = i * 32 + lane;
                const float4 w4 = *reinterpret_cast<const float4*>(&Wt[(c4 ^ tg) << 2]);
                s0 += w4.x * yv[i].x;
                s1 += w4.y * yv[i].y;
                s2 += w4.z * yv[i].z;
                s3 += w4.w * yv[i].w;
                if (c4 == tg) {
                    yt = (t & 1) ? ((t & 2) ? yv[i].w : yv[i].y)
                                 : ((t & 2) ? yv[i].z : yv[i].x);
                }
            }
            pt32 += (s0 + s1) + (s2 + s3);
            if (yt >= 0.0f) ce32 += __logf(yt + 1e-8f);   // one lane per warp

            // (4) issue next y row loads (yv consumed above; lands next iter).
            {
                const float4* ypn = reinterpret_cast<const float4*>(y + (size_t)bn * NCOLS);
                #pragma unroll
                for (int i = 0; i < 8; i++) yv[i] = __ldcs(&ypn[i * 32 + lane]);
            }

            // (5) wait staged target; per-lane compare -> carried (best,bidx).
            asm volatile("cp.async.wait_group 0;");
            best = -1.0f; bidx = 0;
            #pragma unroll
            for (int i = 0; i < 8; i++) {
                const int c4 = i * 32 + lane;
                const float4 v = *reinterpret_cast<const float4*>(tslice + c4 * 16);
                const int base = c4 * 4;
                if (v.x > best) { best = v.x; bidx = base;     }
                if (v.y > best) { best = v.y; bidx = base + 1; }
                if (v.z > best) { best = v.z; bidx = base + 2; }
                if (v.w > best) { best = v.w; bidx = base + 3; }
            }

            if (last) break;
            b = bn;
        }
    }

    // Warp reduce in fp32 (fixed order).
    #pragma unroll
    for (int off = 16; off > 0; off >>= 1) {
        pt32 += __shfl_down_sync(0xffffffffu, pt32, off);
        ce32 += __shfl_down_sync(0xffffffffu, ce32, off);
    }

    // All warps done with W/tbuf -> alias finale storage into the W region.
    __syncthreads();
    double* s_pt = reinterpret_cast<double*>(smem_raw);          // 8 doubles
    double* s_ce = s_pt + 8;                                     // 8 doubles
    int*    flag = reinterpret_cast<int*>(smem_raw + 128);       // is_last
    double* r_pt = reinterpret_cast<double*>(smem_raw + 256);    // 256 doubles
    double* r_ce = r_pt + 256;                                   // 256 doubles

    if (lane == 0) { s_pt[wid] = (double)pt32; s_ce[wid] = (double)ce32; }
    __syncthreads();
    if (tid == 0) {
        double bpt = 0.0, bce = 0.0;
        #pragma unroll
        for (int i = 0; i < 8; i++) { bpt += s_pt[i]; bce += s_ce[i]; }
        g_pt[blockIdx.x] = bpt;
        g_ce[blockIdx.x] = bce;
        __threadfence();
        const unsigned int arrived = atomicAdd(&g_count, 1u);
        *flag = (arrived == NBLK - 1) ? 1 : 0;
    }
    __syncthreads();

    // Last block: final fixed-order reduction -> scalar loss.
    if (*flag) {
        double fpt = 0.0, fce = 0.0;
        for (int i = tid; i < NBLK; i += 256) { fpt += g_pt[i]; fce += g_ce[i]; }
        r_pt[tid] = fpt;
        r_ce[tid] = fce;
        __syncthreads();
        #pragma unroll
        for (int off = 128; off > 0; off >>= 1) {
            if (tid < off) {
                r_pt[tid] += r_pt[tid + off];
                r_ce[tid] += r_ce[tid + off];
            }
            __syncthreads();
        }
        if (tid == 0) {
            const double pt_loss = r_pt[0] / ((double)B * (double)NCOLS);
            const double ce_loss = -r_ce[0] / (double)B;
            out[0] = (float)(ce_loss + pt_loss);
            g_count = 0;   // reset for next graph replay
        }
    }
}

extern "C" void kernel_launch(void* const* d_in, const int* in_sizes, int n_in,
                              void* d_out, int out_size) {
    const float* y_true = (const float*)d_in[0];
    const float* target = (const float*)d_in[1];
    const int B = in_sizes[0] / NCOLS;

    fused_kernel<<<NBLK, 256>>>(y_true, target, (float*)d_out, B);
}